// round 5
// baseline (speedup 1.0000x reference)
#include <cuda_runtime.h>
#include <cuda_fp16.h>

// FernSparseTable v4: double-buffered half-tables (64 KB each), pipelined bulk fills.
//  - g_W16 pre-laid-out as [m][half][row][32 halfs] so each (m,h) half is contiguous 64 KB.
//  - Per fern: phase1 once -> params; per half: wait mbar[h], gathers, sync, issue fill
//    of next fern's same half into the freed buffer. Fill latency fully overlapped.
//  - Gathers: LDS.128, 4 lanes per pixel (16B d-slice), 8 px per instruction, HFMA2,
//    fp32 flush per (half, group) into 64 master accumulators.
//  - Epilogue: stride-65 smem transpose -> coalesced STG.

#define TPB 512
#define PX  512
#define HALF_BYTES 65536
#define PAR_OFF    131072
#define PAR_STRIDE 80
#define MBAR_OFF   (PAR_OFF + PX * PAR_STRIDE)   // 172032
#define SMEM_BYTES (MBAR_OFF + 16)               // 172048

__device__ __align__(128) __half g_W16[16 * 1024 * 64];

// repack weights: fp32 [m][row][64] -> fp16 [m][h][row][32]
__global__ void cvt_kernel(const float4* __restrict__ W)
{
    int i = blockIdx.x * blockDim.x + threadIdx.x;   // 262144 float4
    float4 v = W[i];
    __half2 a = __floats2half2_rn(v.x, v.y);
    __half2 b = __floats2half2_rn(v.z, v.w);
    int m   = i >> 14;
    int rem = i & 16383;
    int row = rem >> 4;
    int q   = rem & 15;
    int h   = q >> 3;
    int qq  = q & 7;
    uint2 r;
    r.x = *reinterpret_cast<unsigned*>(&a);
    r.y = *reinterpret_cast<unsigned*>(&b);
    reinterpret_cast<uint2*>(g_W16)[m * 16384 + h * 8192 + row * 8 + qq] = r;
}

__device__ __forceinline__ __half2 u2h2(unsigned u) {
    return *reinterpret_cast<__half2*>(&u);
}

extern __shared__ char smem_raw[];

__device__ __forceinline__ void mbar_wait(unsigned mbar, unsigned parity)
{
    unsigned done;
    asm volatile(
        "{\n\t.reg .pred p;\n\t"
        "mbarrier.try_wait.parity.acquire.cta.shared::cta.b64 p, [%1], %2;\n\t"
        "selp.b32 %0, 1, 0, p;\n\t}"
        : "=r"(done) : "r"(mbar), "r"(parity) : "memory");
    if (!done) {
        asm volatile(
            "{\n\t.reg .pred P1;\n\t"
            "WL_%=:\n\t"
            "mbarrier.try_wait.parity.acquire.cta.shared::cta.b64 P1, [%0], %1, 0x989680;\n\t"
            "@P1 bra.uni WD_%=;\n\t"
            "bra.uni WL_%=;\n\t"
            "WD_%=:\n\t}"
            :: "r"(mbar), "r"(parity) : "memory");
    }
}

__global__ __launch_bounds__(TPB, 1)
void fern_kernel(const float* __restrict__ B,
                 const float* __restrict__ bias,
                 float* __restrict__ out)
{
    char*  s_par = smem_raw + PAR_OFF;
    float* s_out = (float*)smem_raw;         // epilogue reuse

    const int tid  = threadIdx.x;
    const int lane = tid & 31;
    const int warp = tid >> 5;
    const int pxbase = blockIdx.x * PX;
    const int n      = pxbase >> 12;
    const int hwbase = pxbase & 4095;

    unsigned smem_u32 = (unsigned)__cvta_generic_to_shared(smem_raw);
    const unsigned mb0 = smem_u32 + MBAR_OFF;
    const unsigned mb1 = mb0 + 8;

    const unsigned long long Wg =
        (unsigned long long)__cvta_generic_to_global(g_W16);

    if (tid == 0) {
        asm volatile("mbarrier.init.shared.b64 [%0], 1;" :: "r"(mb0) : "memory");
        asm volatile("mbarrier.init.shared.b64 [%0], 1;" :: "r"(mb1) : "memory");
        asm volatile("fence.proxy.async.shared::cta;" ::: "memory");
        // prime the pipeline: fill (m=0,h=0) into buf0, (m=0,h=1) into buf1
        asm volatile("mbarrier.arrive.expect_tx.shared.b64 _, [%0], %1;"
                     :: "r"(mb0), "r"(HALF_BYTES) : "memory");
        asm volatile("cp.async.bulk.shared::cta.global.mbarrier::complete_tx::bytes "
                     "[%0], [%1], %2, [%3];"
                     :: "r"(smem_u32), "l"(Wg), "r"(HALF_BYTES), "r"(mb0) : "memory");
        asm volatile("mbarrier.arrive.expect_tx.shared.b64 _, [%0], %1;"
                     :: "r"(mb1), "r"(HALF_BYTES) : "memory");
        asm volatile("cp.async.bulk.shared::cta.global.mbarrier::complete_tx::bytes "
                     "[%0], [%1], %2, [%3];"
                     :: "r"(smem_u32 + HALF_BYTES), "l"(Wg + HALF_BYTES),
                        "r"(HALF_BYTES), "r"(mb1) : "memory");
    }

    const float* Bb = B + (n * 160) * 4096 + (hwbase + tid);

    float acc[64];
    #pragma unroll
    for (int i = 0; i < 64; ++i) acc[i] = 0.f;

    const int dslice = (lane & 3) * 16;      // 16B d-slice within a 64B row
    const int px_sub = lane >> 2;            // 0..7

    __syncthreads();   // mbar init visible to all before any wait

    #pragma unroll 1
    for (int m = 0; m < 16; ++m) {
        // ---- phase 1: per-thread fern logic (overlaps in-flight fills) ----
        float t[10];
        #pragma unroll
        for (int k = 0; k < 10; ++k)
            t[k] = Bb[(m * 10 + k) * 4096];

        int wb = 0;
        float bsp = 1.f;
        float ba[10];
        #pragma unroll
        for (int k = 0; k < 10; ++k) {
            if (t[k] >= 0.5f) wb |= (1 << k);
            bsp *= fmaxf(t[k], 1.f - t[k]);
            ba[k] = fabsf(t[k] - 0.5f);
        }

        int abi0, abi1, abi2;
        float av0, av1, av2;
        {
            float best = ba[0]; int bi = 0; float bt = t[0];
            #pragma unroll
            for (int k = 1; k < 10; ++k)
                if (ba[k] < best) { best = ba[k]; bi = k; bt = t[k]; }
            abi0 = bi; av0 = bt;
        }
        {
            float best = 3.0e38f; int bi = 0; float bt = 0.f;
            #pragma unroll
            for (int k = 0; k < 10; ++k)
                if (k != abi0 && ba[k] < best) { best = ba[k]; bi = k; bt = t[k]; }
            abi1 = bi; av1 = bt;
        }
        {
            float best = 3.0e38f; int bi = 0; float bt = 0.f;
            #pragma unroll
            for (int k = 0; k < 10; ++k)
                if (k != abi0 && k != abi1 && ba[k] < best) { best = ba[k]; bi = k; bt = t[k]; }
            abi2 = bi; av2 = bt;
        }

        const float d0 = 1.f - av0, d1 = 1.f - av1, d2 = 1.f - av2;
        const float denom = fmaxf(av0, d0) * fmaxf(av1, d1) * fmaxf(av2, d2);
        const float bspp = bsp / denom;

        float cp[8];
        {
            float g0 = bspp * d0,  g1 = bspp * av0;
            float c00 = g0 * d1,  c10 = g1 * d1;
            float c01 = g0 * av1, c11 = g1 * av1;
            cp[0] = c00 * d2;  cp[1] = c10 * d2;  cp[2] = c01 * d2;  cp[3] = c11 * d2;
            cp[4] = c00 * av2; cp[5] = c10 * av2; cp[6] = c01 * av2; cp[7] = c11 * av2;
        }
        unsigned ch[8];
        #pragma unroll
        for (int j = 0; j < 8; ++j) {
            __half2 hh = __floats2half2_rn(cp[j], cp[j]);
            ch[j] = *reinterpret_cast<unsigned*>(&hh);
        }
        int io[8];
        {
            const int m0 = 1 << abi0, m1 = 1 << abi1, m2 = 1 << abi2;
            const int b0 = wb & ~(m0 | m1 | m2);
            const int i0 = b0, i1 = b0 | m0, i2 = b0 | m1, i3 = b0 | m0 | m1;
            io[0] = i0 << 6;        io[1] = i1 << 6;    // 64B rows in half-tables
            io[2] = i2 << 6;        io[3] = i3 << 6;
            io[4] = (i0 | m2) << 6; io[5] = (i1 | m2) << 6;
            io[6] = (i2 | m2) << 6; io[7] = (i3 | m2) << 6;
        }
        {
            uint4* myp = (uint4*)(s_par + tid * PAR_STRIDE);
            #pragma unroll
            for (int jj = 0; jj < 4; ++jj)
                myp[jj] = make_uint4(ch[2*jj], (unsigned)io[2*jj],
                                     ch[2*jj+1], (unsigned)io[2*jj+1]);
        }
        __syncwarp();   // params are only read warp-locally

        const unsigned parity = (unsigned)(m & 1);

        #pragma unroll
        for (int h = 0; h < 2; ++h) {
            mbar_wait(h ? mb1 : mb0, parity);

            const char* gl = smem_raw + h * HALF_BYTES + dslice;

            #pragma unroll
            for (int g = 0; g < 4; ++g) {
                const uint4* pp =
                    (const uint4*)(s_par + (warp * 32 + g * 8 + px_sub) * PAR_STRIDE);
                __half2 h0 = __floats2half2_rn(0.f, 0.f);
                __half2 h1 = h0, h2 = h0, h3 = h0;
                #pragma unroll
                for (int jj = 0; jj < 4; ++jj) {
                    uint4 pr = pp[jj];
                    {
                        __half2 c = u2h2(pr.x);
                        uint4 w4 = *(const uint4*)(gl + pr.y);
                        h0 = __hfma2(c, u2h2(w4.x), h0);
                        h1 = __hfma2(c, u2h2(w4.y), h1);
                        h2 = __hfma2(c, u2h2(w4.z), h2);
                        h3 = __hfma2(c, u2h2(w4.w), h3);
                    }
                    {
                        __half2 c = u2h2(pr.z);
                        uint4 w4 = *(const uint4*)(gl + pr.w);
                        h0 = __hfma2(c, u2h2(w4.x), h0);
                        h1 = __hfma2(c, u2h2(w4.y), h1);
                        h2 = __hfma2(c, u2h2(w4.z), h2);
                        h3 = __hfma2(c, u2h2(w4.w), h3);
                    }
                }
                float2 f0 = __half22float2(h0);
                float2 f1 = __half22float2(h1);
                float2 f2 = __half22float2(h2);
                float2 f3 = __half22float2(h3);
                const int ab = h * 32 + g * 8;
                acc[ab+0] += f0.x; acc[ab+1] += f0.y;
                acc[ab+2] += f1.x; acc[ab+3] += f1.y;
                acc[ab+4] += f2.x; acc[ab+5] += f2.y;
                acc[ab+6] += f3.x; acc[ab+7] += f3.y;
            }

            __syncthreads();   // buffer h consumed by all warps

            if (m < 15 && tid == 0) {
                const unsigned mb = h ? mb1 : mb0;
                unsigned long long src =
                    Wg + (unsigned long long)((m + 1) * 2 + h) * HALF_BYTES;
                asm volatile("mbarrier.arrive.expect_tx.shared.b64 _, [%0], %1;"
                             :: "r"(mb), "r"(HALF_BYTES) : "memory");
                asm volatile("cp.async.bulk.shared::cta.global.mbarrier::complete_tx::bytes "
                             "[%0], [%1], %2, [%3];"
                             :: "r"(smem_u32 + h * HALF_BYTES), "l"(src),
                                "r"(HALF_BYTES), "r"(mb) : "memory");
            }
        }
    }

    // ---- epilogue: stride-65 transpose -> coalesced stores ----
    // (last task ended with __syncthreads; buffers free for reuse)
    #pragma unroll
    for (int h = 0; h < 2; ++h)
        #pragma unroll
        for (int g = 0; g < 4; ++g) {
            int px = warp * 32 + g * 8 + px_sub;
            float* row = s_out + px * 65 + h * 32 + (lane & 3) * 8;
            #pragma unroll
            for (int r = 0; r < 8; ++r) row[r] = acc[h * 32 + g * 8 + r];
        }
    __syncthreads();

    {
        const float* srow = s_out + tid * 65;
        float* obase = out + (n * 64) * 4096 + hwbase + tid;
        #pragma unroll
        for (int d = 0; d < 64; ++d)
            obase[d * 4096] = srow[d] + bias[d];
    }
}

extern "C" void kernel_launch(void* const* d_in, const int* in_sizes, int n_in,
                              void* d_out, int out_size)
{
    const float* B    = (const float*)d_in[0];
    const float* W    = (const float*)d_in[1];
    const float* bias = (const float*)d_in[2];
    float* out = (float*)d_out;

    cvt_kernel<<<1024, 256>>>((const float4*)W);

    cudaFuncSetAttribute(fern_kernel, cudaFuncAttributeMaxDynamicSharedMemorySize, SMEM_BYTES);
    fern_kernel<<<256, TPB, SMEM_BYTES>>>(B, bias, out);
}

// round 7
// speedup vs baseline: 1.3557x; 1.3557x over previous
#include <cuda_runtime.h>
#include <cuda_fp16.h>

// FernSparseTable v5: v3 gather geometry (128-B rows, full fp16 table, single buffer)
//  + cross-fern B prefetch + balanced 296-CTA grid (2 exact waves of 148).

#define TPB 512
#define NPX 131072
#define NCTA 296
#define PX_PER 443                   // ceil(131072/296); last CTA gets 387
#define TAB_BYTES 131072             // 1024 rows * 128 B
#define PAR_STRIDE 80                // 8 probes * 8B + 16B pad
#define MBAR_OFF  (TAB_BYTES + TPB * PAR_STRIDE)   // 172032
#define SMEM_BYTES (MBAR_OFF + 16)                 // 172048

__device__ __align__(128) __half g_W16[16 * 1024 * 64];

__global__ void cvt_kernel(const float4* __restrict__ W)
{
    int i = blockIdx.x * blockDim.x + threadIdx.x;   // 262144 float4
    float4 v = W[i];
    __half2 a = __floats2half2_rn(v.x, v.y);
    __half2 b = __floats2half2_rn(v.z, v.w);
    uint2 r;
    r.x = *reinterpret_cast<unsigned*>(&a);
    r.y = *reinterpret_cast<unsigned*>(&b);
    reinterpret_cast<uint2*>(g_W16)[i] = r;
}

__device__ __forceinline__ __half2 u2h2(unsigned u) {
    return *reinterpret_cast<__half2*>(&u);
}

extern __shared__ char smem_raw[];

__device__ __forceinline__ void mbar_wait(unsigned mbar, unsigned parity)
{
    unsigned done;
    asm volatile(
        "{\n\t.reg .pred p;\n\t"
        "mbarrier.try_wait.parity.acquire.cta.shared::cta.b64 p, [%1], %2;\n\t"
        "selp.b32 %0, 1, 0, p;\n\t}"
        : "=r"(done) : "r"(mbar), "r"(parity) : "memory");
    if (!done) {
        asm volatile(
            "{\n\t.reg .pred P1;\n\t"
            "WL_%=:\n\t"
            "mbarrier.try_wait.parity.acquire.cta.shared::cta.b64 P1, [%0], %1, 0x989680;\n\t"
            "@P1 bra.uni WD_%=;\n\t"
            "bra.uni WL_%=;\n\t"
            "WD_%=:\n\t}"
            :: "r"(mbar), "r"(parity) : "memory");
    }
}

__global__ __launch_bounds__(TPB, 1)
void fern_kernel(const float* __restrict__ B,
                 const float* __restrict__ bias,
                 float* __restrict__ out)
{
    char*  s_tab = smem_raw;
    char*  s_par = smem_raw + TAB_BYTES;
    float* s_out = (float*)smem_raw;         // epilogue reuse

    const int tid  = threadIdx.x;
    const int lane = tid & 31;
    const int warp = tid >> 5;

    const int base = blockIdx.x * PX_PER;
    const int cnt  = min(PX_PER, NPX - base);       // 443 or 387
    const int px   = min(base + tid, NPX - 1);      // clamped pixel id
    const bool valid = (base + tid) < NPX && tid < cnt;
    const int n  = px >> 12;
    const int hw = px & 4095;

    unsigned smem_u32 = (unsigned)__cvta_generic_to_shared(smem_raw);
    const unsigned mbar = smem_u32 + MBAR_OFF;

    if (tid == 0) {
        asm volatile("mbarrier.init.shared.b64 [%0], 1;" :: "r"(mbar) : "memory");
        asm volatile("fence.proxy.async.shared::cta;" ::: "memory");
    }

    const float* Bb = B + (n * 160) * 4096 + hw;
    const unsigned long long Wg =
        (unsigned long long)__cvta_generic_to_global(g_W16);

    float acc[64];
    #pragma unroll
    for (int i = 0; i < 64; ++i) acc[i] = 0.f;

    const char* gl = s_tab + (lane & 7) * 16;    // lane's 16B d-slice in a 128B row
    const int px_sub = lane >> 3;                // 0..3

    // prime: B values for fern 0
    float t[10];
    #pragma unroll
    for (int k = 0; k < 10; ++k)
        t[k] = Bb[k * 4096];

    #pragma unroll 1
    for (int m = 0; m < 16; ++m) {
        __syncthreads();   // prev fern's gathers done; mbar init visible (m=0)

        // ---- issue bulk fill of fern m's table ----
        if (tid == 0) {
            asm volatile("mbarrier.arrive.expect_tx.shared.b64 _, [%0], %1;"
                         :: "r"(mbar), "r"(TAB_BYTES) : "memory");
            unsigned long long src = Wg + (unsigned long long)m * 131072ull;
            #pragma unroll
            for (int c = 0; c < 4; ++c) {
                asm volatile(
                    "cp.async.bulk.shared::cta.global.mbarrier::complete_tx::bytes "
                    "[%0], [%1], %2, [%3];"
                    :: "r"(smem_u32 + c * 32768), "l"(src + c * 32768ull),
                       "r"(32768), "r"(mbar) : "memory");
            }
        }

        // ---- prefetch B for fern m+1 (hidden behind fill wait + gathers) ----
        float tn[10];
        {
            const int mn = (m < 15) ? (m + 1) : 15;
            #pragma unroll
            for (int k = 0; k < 10; ++k)
                tn[k] = Bb[(mn * 10 + k) * 4096];
        }

        // ---- phase 1: fern logic on registers ----
        int wb = 0;
        float bsp = 1.f;
        #pragma unroll
        for (int k = 0; k < 10; ++k) {
            if (t[k] >= 0.5f) wb |= (1 << k);
            bsp *= fmaxf(t[k], 1.f - t[k]);
        }

        int abi0, abi1, abi2;
        float av0, av1, av2;
        {
            float best = fabsf(t[0] - 0.5f); int bi = 0; float bt = t[0];
            #pragma unroll
            for (int k = 1; k < 10; ++k) {
                float ak = fabsf(t[k] - 0.5f);
                if (ak < best) { best = ak; bi = k; bt = t[k]; }
            }
            abi0 = bi; av0 = bt;
        }
        {
            float best = 3.0e38f; int bi = 0; float bt = 0.f;
            #pragma unroll
            for (int k = 0; k < 10; ++k) {
                float ak = fabsf(t[k] - 0.5f);
                if (k != abi0 && ak < best) { best = ak; bi = k; bt = t[k]; }
            }
            abi1 = bi; av1 = bt;
        }
        {
            float best = 3.0e38f; int bi = 0; float bt = 0.f;
            #pragma unroll
            for (int k = 0; k < 10; ++k) {
                float ak = fabsf(t[k] - 0.5f);
                if (k != abi0 && k != abi1 && ak < best) { best = ak; bi = k; bt = t[k]; }
            }
            abi2 = bi; av2 = bt;
        }

        const float d0 = 1.f - av0, d1 = 1.f - av1, d2 = 1.f - av2;
        const float denom = fmaxf(av0, d0) * fmaxf(av1, d1) * fmaxf(av2, d2);
        const float bspp = valid ? (bsp / denom) : 0.f;

        float cp[8];
        {
            float g0 = bspp * d0,  g1 = bspp * av0;
            float c00 = g0 * d1,  c10 = g1 * d1;
            float c01 = g0 * av1, c11 = g1 * av1;
            cp[0] = c00 * d2;  cp[1] = c10 * d2;  cp[2] = c01 * d2;  cp[3] = c11 * d2;
            cp[4] = c00 * av2; cp[5] = c10 * av2; cp[6] = c01 * av2; cp[7] = c11 * av2;
        }
        unsigned ch[8];
        #pragma unroll
        for (int j = 0; j < 8; ++j) {
            __half2 hh = __floats2half2_rn(cp[j], cp[j]);
            ch[j] = *reinterpret_cast<unsigned*>(&hh);
        }
        int io[8];
        {
            const int m0 = 1 << abi0, m1 = 1 << abi1, m2 = 1 << abi2;
            const int b0 = wb & ~(m0 | m1 | m2);
            const int i0 = b0, i1 = b0 | m0, i2 = b0 | m1, i3 = b0 | m0 | m1;
            io[0] = i0 << 7;        io[1] = i1 << 7;
            io[2] = i2 << 7;        io[3] = i3 << 7;
            io[4] = (i0 | m2) << 7; io[5] = (i1 | m2) << 7;
            io[6] = (i2 | m2) << 7; io[7] = (i3 | m2) << 7;
        }

        {
            uint4* myp = (uint4*)(s_par + tid * PAR_STRIDE);
            #pragma unroll
            for (int jj = 0; jj < 4; ++jj)
                myp[jj] = make_uint4(ch[2*jj], (unsigned)io[2*jj],
                                     ch[2*jj+1], (unsigned)io[2*jj+1]);
        }
        __syncwarp();   // params read only warp-locally

        mbar_wait(mbar, (unsigned)(m & 1));

        // ---- phase 2: HFMA2 gathers, 4 px per instruction; tail groups skipped ----
        #pragma unroll
        for (int g = 0; g < 8; ++g) {
            if (warp * 32 + g * 4 < cnt) {       // warp-uniform guard
                const uint4* pp =
                    (const uint4*)(s_par + (warp * 32 + g * 4 + px_sub) * PAR_STRIDE);
                __half2 h0 = __floats2half2_rn(0.f, 0.f);
                __half2 h1 = h0, h2 = h0, h3 = h0;
                #pragma unroll
                for (int jj = 0; jj < 4; ++jj) {
                    uint4 pr = pp[jj];
                    {
                        __half2 c = u2h2(pr.x);
                        uint4 w4 = *(const uint4*)(gl + pr.y);
                        h0 = __hfma2(c, u2h2(w4.x), h0);
                        h1 = __hfma2(c, u2h2(w4.y), h1);
                        h2 = __hfma2(c, u2h2(w4.z), h2);
                        h3 = __hfma2(c, u2h2(w4.w), h3);
                    }
                    {
                        __half2 c = u2h2(pr.z);
                        uint4 w4 = *(const uint4*)(gl + pr.w);
                        h0 = __hfma2(c, u2h2(w4.x), h0);
                        h1 = __hfma2(c, u2h2(w4.y), h1);
                        h2 = __hfma2(c, u2h2(w4.z), h2);
                        h3 = __hfma2(c, u2h2(w4.w), h3);
                    }
                }
                float2 f0 = __half22float2(h0);
                float2 f1 = __half22float2(h1);
                float2 f2 = __half22float2(h2);
                float2 f3 = __half22float2(h3);
                acc[g*8+0] += f0.x; acc[g*8+1] += f0.y;
                acc[g*8+2] += f1.x; acc[g*8+3] += f1.y;
                acc[g*8+4] += f2.x; acc[g*8+5] += f2.y;
                acc[g*8+6] += f3.x; acc[g*8+7] += f3.y;
            }
        }

        #pragma unroll
        for (int k = 0; k < 10; ++k) t[k] = tn[k];
    }

    // ---- epilogue: stride-65 transpose -> coalesced stores ----
    __syncthreads();
    #pragma unroll
    for (int g = 0; g < 8; ++g) {
        int pxl = warp * 32 + g * 4 + px_sub;
        float* row = s_out + pxl * 65 + (lane & 7) * 8;
        #pragma unroll
        for (int r = 0; r < 8; ++r) row[r] = acc[g * 8 + r];
    }
    __syncthreads();

    if (valid) {
        const float* srow = s_out + tid * 65;
        float* obase = out + (n * 64) * 4096 + hw;
        #pragma unroll
        for (int d = 0; d < 64; ++d)
            obase[d * 4096] = srow[d] + bias[d];
    }
}

extern "C" void kernel_launch(void* const* d_in, const int* in_sizes, int n_in,
                              void* d_out, int out_size)
{
    const float* B    = (const float*)d_in[0];
    const float* W    = (const float*)d_in[1];
    const float* bias = (const float*)d_in[2];
    float* out = (float*)d_out;

    cvt_kernel<<<1024, 256>>>((const float4*)W);

    cudaFuncSetAttribute(fern_kernel, cudaFuncAttributeMaxDynamicSharedMemorySize, SMEM_BYTES);
    fern_kernel<<<NCTA, TPB, SMEM_BYTES>>>(B, bias, out);
}

// round 8
// speedup vs baseline: 1.4000x; 1.0327x over previous
#include <cuda_runtime.h>
#include <cuda_fp16.h>

// FernSparseTable v6: v5 + split-barrier fill gate and phase rotation.
//  Loop: wait(m) -> gathers(m) -> bar.arrive (warp0: bar.sync + issue fill(m+1))
//        -> prefetch B(m+2) -> phase1(m+1) -> STS params.
//  Early warps overlap their phase-1 with other warps' gathers; crossbar stays fed.

#define TPB 512
#define NPX 131072
#define NCTA 296
#define PX_PER 443                   // ceil(131072/296); last CTA gets 387
#define TAB_BYTES 131072             // 1024 rows * 128 B
#define PAR_STRIDE 80                // 8 probes * 8B + 16B pad
#define MBAR_OFF  (TAB_BYTES + TPB * PAR_STRIDE)   // 172032
#define SMEM_BYTES (MBAR_OFF + 16)                 // 172048

__device__ __align__(128) __half g_W16[16 * 1024 * 64];

__global__ void cvt_kernel(const float4* __restrict__ W)
{
    int i = blockIdx.x * blockDim.x + threadIdx.x;   // 262144 float4
    float4 v = W[i];
    __half2 a = __floats2half2_rn(v.x, v.y);
    __half2 b = __floats2half2_rn(v.z, v.w);
    uint2 r;
    r.x = *reinterpret_cast<unsigned*>(&a);
    r.y = *reinterpret_cast<unsigned*>(&b);
    reinterpret_cast<uint2*>(g_W16)[i] = r;
}

__device__ __forceinline__ __half2 u2h2(unsigned u) {
    return *reinterpret_cast<__half2*>(&u);
}

extern __shared__ char smem_raw[];

__device__ __forceinline__ void mbar_wait(unsigned mbar, unsigned parity)
{
    unsigned done;
    asm volatile(
        "{\n\t.reg .pred p;\n\t"
        "mbarrier.try_wait.parity.acquire.cta.shared::cta.b64 p, [%1], %2;\n\t"
        "selp.b32 %0, 1, 0, p;\n\t}"
        : "=r"(done) : "r"(mbar), "r"(parity) : "memory");
    if (!done) {
        asm volatile(
            "{\n\t.reg .pred P1;\n\t"
            "WL_%=:\n\t"
            "mbarrier.try_wait.parity.acquire.cta.shared::cta.b64 P1, [%0], %1, 0x989680;\n\t"
            "@P1 bra.uni WD_%=;\n\t"
            "bra.uni WL_%=;\n\t"
            "WD_%=:\n\t}"
            :: "r"(mbar), "r"(parity) : "memory");
    }
}

__global__ __launch_bounds__(TPB, 1)
void fern_kernel(const float* __restrict__ B,
                 const float* __restrict__ bias,
                 float* __restrict__ out)
{
    char*  s_tab = smem_raw;
    char*  s_par = smem_raw + TAB_BYTES;
    float* s_out = (float*)smem_raw;         // epilogue reuse

    const int tid  = threadIdx.x;
    const int lane = tid & 31;
    const int warp = tid >> 5;

    const int base = blockIdx.x * PX_PER;
    const int cnt  = min(PX_PER, NPX - base);       // 443 or 387
    const int px   = min(base + tid, NPX - 1);      // clamped pixel id
    const bool valid = (base + tid) < NPX && tid < cnt;
    const int n  = px >> 12;
    const int hw = px & 4095;
    const int rem = cnt - warp * 32;                // per-warp tail bound

    unsigned smem_u32 = (unsigned)__cvta_generic_to_shared(smem_raw);
    const unsigned mbar = smem_u32 + MBAR_OFF;

    if (tid == 0) {
        asm volatile("mbarrier.init.shared.b64 [%0], 1;" :: "r"(mbar) : "memory");
        asm volatile("fence.proxy.async.shared::cta;" ::: "memory");
    }

    const float* Bb = B + (n * 160) * 4096 + hw;
    const unsigned long long Wg =
        (unsigned long long)__cvta_generic_to_global(g_W16);

    float acc[64];
    #pragma unroll
    for (int i = 0; i < 64; ++i) acc[i] = 0.f;

    const char* gl = s_tab + (lane & 7) * 16;    // lane's 16B d-slice in a 128B row
    const int px_sub = lane >> 3;                // 0..3

    // fill-issue helper (tid 0 only)
    auto issue_fill = [&](int m) {
        asm volatile("mbarrier.arrive.expect_tx.shared.b64 _, [%0], %1;"
                     :: "r"(mbar), "r"(TAB_BYTES) : "memory");
        unsigned long long src = Wg + (unsigned long long)m * 131072ull;
        #pragma unroll
        for (int c = 0; c < 4; ++c) {
            asm volatile(
                "cp.async.bulk.shared::cta.global.mbarrier::complete_tx::bytes "
                "[%0], [%1], %2, [%3];"
                :: "r"(smem_u32 + c * 32768), "l"(src + c * 32768ull),
                   "r"(32768), "r"(mbar) : "memory");
        }
    };

    // phase-1: fern logic on register array tv -> params in smem (warp-local)
    auto phase1 = [&](const float* tv) {
        int wb = 0;
        float bsp = 1.f;
        #pragma unroll
        for (int k = 0; k < 10; ++k) {
            if (tv[k] >= 0.5f) wb |= (1 << k);
            bsp *= fmaxf(tv[k], 1.f - tv[k]);
        }
        int abi0, abi1, abi2;
        float av0, av1, av2;
        {
            float best = fabsf(tv[0] - 0.5f); int bi = 0; float bt = tv[0];
            #pragma unroll
            for (int k = 1; k < 10; ++k) {
                float ak = fabsf(tv[k] - 0.5f);
                if (ak < best) { best = ak; bi = k; bt = tv[k]; }
            }
            abi0 = bi; av0 = bt;
        }
        {
            float best = 3.0e38f; int bi = 0; float bt = 0.f;
            #pragma unroll
            for (int k = 0; k < 10; ++k) {
                float ak = fabsf(tv[k] - 0.5f);
                if (k != abi0 && ak < best) { best = ak; bi = k; bt = tv[k]; }
            }
            abi1 = bi; av1 = bt;
        }
        {
            float best = 3.0e38f; int bi = 0; float bt = 0.f;
            #pragma unroll
            for (int k = 0; k < 10; ++k) {
                float ak = fabsf(tv[k] - 0.5f);
                if (k != abi0 && k != abi1 && ak < best) { best = ak; bi = k; bt = tv[k]; }
            }
            abi2 = bi; av2 = bt;
        }

        const float d0 = 1.f - av0, d1 = 1.f - av1, d2 = 1.f - av2;
        const float denom = fmaxf(av0, d0) * fmaxf(av1, d1) * fmaxf(av2, d2);
        const float bspp = valid ? (bsp / denom) : 0.f;

        float cp[8];
        {
            float g0 = bspp * d0,  g1 = bspp * av0;
            float c00 = g0 * d1,  c10 = g1 * d1;
            float c01 = g0 * av1, c11 = g1 * av1;
            cp[0] = c00 * d2;  cp[1] = c10 * d2;  cp[2] = c01 * d2;  cp[3] = c11 * d2;
            cp[4] = c00 * av2; cp[5] = c10 * av2; cp[6] = c01 * av2; cp[7] = c11 * av2;
        }
        unsigned ch[8];
        #pragma unroll
        for (int j = 0; j < 8; ++j) {
            __half2 hh = __floats2half2_rn(cp[j], cp[j]);
            ch[j] = *reinterpret_cast<unsigned*>(&hh);
        }
        int io[8];
        {
            const int m0 = 1 << abi0, m1 = 1 << abi1, m2 = 1 << abi2;
            const int b0 = wb & ~(m0 | m1 | m2);
            const int i0 = b0, i1 = b0 | m0, i2 = b0 | m1, i3 = b0 | m0 | m1;
            io[0] = i0 << 7;        io[1] = i1 << 7;
            io[2] = i2 << 7;        io[3] = i3 << 7;
            io[4] = (i0 | m2) << 7; io[5] = (i1 | m2) << 7;
            io[6] = (i2 | m2) << 7; io[7] = (i3 | m2) << 7;
        }
        uint4* myp = (uint4*)(s_par + tid * PAR_STRIDE);
        #pragma unroll
        for (int jj = 0; jj < 4; ++jj)
            myp[jj] = make_uint4(ch[2*jj], (unsigned)io[2*jj],
                                 ch[2*jj+1], (unsigned)io[2*jj+1]);
        __syncwarp();
    };

    // ---- prologue: load fern 0 + 1 B values, phase1(0), start fill(0) ----
    float tc[10], tn[10];
    #pragma unroll
    for (int k = 0; k < 10; ++k) tc[k] = Bb[k * 4096];
    {
        const float* pf = Bb + 40960;
        #pragma unroll
        for (int k = 0; k < 10; ++k) tn[k] = pf[k * 4096];
    }
    phase1(tc);
    __syncthreads();            // mbar init visible before any wait
    if (tid == 0) issue_fill(0);

    #pragma unroll 1
    for (int m = 0; m < 16; ++m) {
        mbar_wait(mbar, (unsigned)(m & 1));

        // ---- phase 2: HFMA2 gathers, 4 px per instruction; tail groups skipped ----
        #pragma unroll
        for (int g = 0; g < 8; ++g) {
            if (g * 4 < rem) {                    // warp-uniform guard
                const uint4* pp =
                    (const uint4*)(s_par + (warp * 32 + g * 4 + px_sub) * PAR_STRIDE);
                __half2 h0 = __floats2half2_rn(0.f, 0.f);
                __half2 h1 = h0, h2 = h0, h3 = h0;
                #pragma unroll
                for (int jj = 0; jj < 4; ++jj) {
                    uint4 pr = pp[jj];
                    {
                        __half2 c = u2h2(pr.x);
                        uint4 w4 = *(const uint4*)(gl + pr.y);
                        h0 = __hfma2(c, u2h2(w4.x), h0);
                        h1 = __hfma2(c, u2h2(w4.y), h1);
                        h2 = __hfma2(c, u2h2(w4.z), h2);
                        h3 = __hfma2(c, u2h2(w4.w), h3);
                    }
                    {
                        __half2 c = u2h2(pr.z);
                        uint4 w4 = *(const uint4*)(gl + pr.w);
                        h0 = __hfma2(c, u2h2(w4.x), h0);
                        h1 = __hfma2(c, u2h2(w4.y), h1);
                        h2 = __hfma2(c, u2h2(w4.z), h2);
                        h3 = __hfma2(c, u2h2(w4.w), h3);
                    }
                }
                float2 f0 = __half22float2(h0);
                float2 f1 = __half22float2(h1);
                float2 f2 = __half22float2(h2);
                float2 f3 = __half22float2(h3);
                acc[g*8+0] += f0.x; acc[g*8+1] += f0.y;
                acc[g*8+2] += f1.x; acc[g*8+3] += f1.y;
                acc[g*8+4] += f2.x; acc[g*8+5] += f2.y;
                acc[g*8+6] += f3.x; acc[g*8+7] += f3.y;
            }
        }

        if (m < 15) {
            // table-free gate: warps 1-15 arrive and proceed; warp 0 waits for all,
            // then issues the next fill. Early warps overlap phase-1 with late gathers.
            if (warp == 0) {
                asm volatile("bar.sync 1, 512;" ::: "memory");
                if (tid == 0) issue_fill(m + 1);
            } else {
                asm volatile("bar.arrive 1, 512;" ::: "memory");
            }

            // prefetch B for fern m+2
            float t2[10];
            {
                const int mn = (m + 2 < 16) ? (m + 2) : 15;
                const float* pf = Bb + mn * 40960;
                #pragma unroll
                for (int k = 0; k < 10; ++k) t2[k] = pf[k * 4096];
            }

            phase1(tn);           // fern m+1 params

            #pragma unroll
            for (int k = 0; k < 10; ++k) tn[k] = t2[k];
        }
    }

    // ---- epilogue: stride-65 transpose -> coalesced stores ----
    __syncthreads();
    #pragma unroll
    for (int g = 0; g < 8; ++g) {
        int pxl = warp * 32 + g * 4 + px_sub;
        float* row = s_out + pxl * 65 + (lane & 7) * 8;
        #pragma unroll
        for (int r = 0; r < 8; ++r) row[r] = acc[g * 8 + r];
    }
    __syncthreads();

    if (valid) {
        const float* srow = s_out + tid * 65;
        float* obase = out + (n * 64) * 4096 + hw;
        #pragma unroll
        for (int d = 0; d < 64; ++d)
            obase[d * 4096] = srow[d] + bias[d];
    }
}

extern "C" void kernel_launch(void* const* d_in, const int* in_sizes, int n_in,
                              void* d_out, int out_size)
{
    const float* B    = (const float*)d_in[0];
    const float* W    = (const float*)d_in[1];
    const float* bias = (const float*)d_in[2];
    float* out = (float*)d_out;

    cvt_kernel<<<1024, 256>>>((const float4*)W);

    cudaFuncSetAttribute(fern_kernel, cudaFuncAttributeMaxDynamicSharedMemorySize, SMEM_BYTES);
    fern_kernel<<<NCTA, TPB, SMEM_BYTES>>>(B, bias, out);
}